// round 1
// baseline (speedup 1.0000x reference)
#include <cuda_runtime.h>
#include <cuda_bf16.h>

// Problem constants (fixed by the dataset's setup_inputs):
//   feature_maps: [1, 200, 304, 256] fp32   (NHWC, C innermost)
//   proposals:    [N, 4] fp32 (x1, y1, x2, y2) in image pixel coords
//   image_shape:  [2] int32 (H_img=800, W_img=1216)
//   output:       [N, 7, 7, 256] fp32
#define HF   200
#define WF   304
#define CC   256
#define CROP 14
#define POOL 7

struct __align__(16) Axis {
    int   i0;   // clipped floor index
    int   i1;   // clipped floor+1 index
    float l;    // interpolation fraction (from UNclipped floor)
    float v;    // validity (1.0f if in [0, dim-1] else 0.0f)
};

__device__ __forceinline__ float4 lerp4(float4 a, float4 b, float t) {
    float4 r;
    r.x = fmaf(b.x - a.x, t, a.x);
    r.y = fmaf(b.y - a.y, t, a.y);
    r.z = fmaf(b.z - a.z, t, a.z);
    r.w = fmaf(b.w - a.w, t, a.w);
    return r;
}

__device__ __forceinline__ float4 max4(float4 a, float4 b) {
    float4 r;
    r.x = fmaxf(a.x, b.x);
    r.y = fmaxf(a.y, b.y);
    r.z = fmaxf(a.z, b.z);
    r.w = fmaxf(a.w, b.w);
    return r;
}

__global__ __launch_bounds__(256, 8)
void roi_pool_kernel(const float* __restrict__ fm,
                     const float* __restrict__ props,
                     const int*   __restrict__ ishape,
                     float* __restrict__ out,
                     int N)
{
    __shared__ Axis sy[CROP];
    __shared__ Axis sx[CROP];

    const int n   = blockIdx.x;
    const int tx  = threadIdx.x;                    // 0..63: channel group (float4)
    const int ty  = threadIdx.y;                    // 0..3 : pooled-cell slice
    const int tid = ty * 64 + tx;

    // ---- Per-box axis parameters (28 threads, once per box) ----
    if (tid < 2 * CROP) {
        const float h = (float)ishape[0];
        const float w = (float)ishape[1];
        const float* p = props + (size_t)n * 4;
        const bool isY = (tid < CROP);
        const int  i   = isY ? tid : tid - CROP;
        // normalized coords: boxes = [y1/h, x1/w, y2/h, x2/w]
        const float c1 = isY ? (p[1] / h) : (p[0] / w);
        const float c2 = isY ? (p[3] / h) : (p[2] / w);
        const float D  = isY ? (float)(HF - 1) : (float)(WF - 1);
        // s = c1*D + i * ((c2-c1)*D/(crop-1))   (matches reference exactly)
        const float step = (c2 - c1) * D / (float)(CROP - 1);
        const float s    = fmaf((float)i, step, c1 * D);
        const float f    = floorf(s);
        int i0 = (int)f;
        i0 = max(0, min(i0, (int)D));
        const int i1 = min(i0 + 1, (int)D);
        Axis a;
        a.i0 = i0;
        a.i1 = i1;
        a.l  = s - f;
        a.v  = (s >= 0.0f && s <= D) ? 1.0f : 0.0f;
        if (isY) sy[i] = a; else sx[i] = a;
    }
    __syncthreads();

    const int coff = tx * 4;  // channel offset for this lane's float4

    // ---- 49 pooled cells, strided over threadIdx.y ----
    for (int cell = ty; cell < POOL * POOL; cell += 4) {
        const int py = cell / POOL;
        const int px = cell - py * POOL;

        float4 m;
        bool first = true;

        #pragma unroll
        for (int dy = 0; dy < 2; ++dy) {
            const Axis ay = sy[2 * py + dy];
            const float* r0 = fm + ((size_t)ay.i0 * WF) * CC;
            const float* r1 = fm + ((size_t)ay.i1 * WF) * CC;
            #pragma unroll
            for (int dx = 0; dx < 2; ++dx) {
                const Axis ax = sx[2 * px + dx];
                const float4 v00 = *(const float4*)(r0 + (size_t)ax.i0 * CC + coff);
                const float4 v01 = *(const float4*)(r0 + (size_t)ax.i1 * CC + coff);
                const float4 v10 = *(const float4*)(r1 + (size_t)ax.i0 * CC + coff);
                const float4 v11 = *(const float4*)(r1 + (size_t)ax.i1 * CC + coff);

                const float lx = ax.l;
                const float ly = ay.l;
                float4 top = lerp4(v00, v01, lx);
                float4 bot = lerp4(v10, v11, lx);
                float4 val = lerp4(top, bot, ly);

                const bool valid = (ay.v * ax.v) != 0.0f;
                if (!valid) { val.x = 0.f; val.y = 0.f; val.z = 0.f; val.w = 0.f; }

                m = first ? val : max4(m, val);
                first = false;
            }
        }

        float* o = out + (((size_t)n * (POOL * POOL)) + cell) * CC + coff;
        *(float4*)o = m;
    }
}

extern "C" void kernel_launch(void* const* d_in, const int* in_sizes, int n_in,
                              void* d_out, int out_size) {
    const float* fm     = (const float*)d_in[0];
    const float* props  = (const float*)d_in[1];
    const int*   ishape = (const int*)  d_in[2];
    float*       out    = (float*)d_out;

    const int N = in_sizes[1] / 4;   // proposals: [N, 4]

    dim3 block(64, 4, 1);
    dim3 grid(N, 1, 1);
    roi_pool_kernel<<<grid, block>>>(fm, props, ishape, out, N);
}

// round 2
// speedup vs baseline: 2.7048x; 2.7048x over previous
#include <cuda_runtime.h>
#include <cuda_bf16.h>

// feature_maps: [1, 200, 304, 256] fp32 (NHWC) | proposals: [N,4] (x1,y1,x2,y2)
// image_shape: [2] int32 | output: [N, 7, 7, 256] fp32
#define HF   200
#define WF   304
#define CC   256
#define CROP 14
#define POOL 7

struct __align__(16) Axis {
    int   i0;   // clipped floor index
    int   i1;   // clipped floor+1 index
    float l;    // interpolation fraction (from UNclipped floor)
    float v;    // validity (1.0f if in [0, dim-1] else 0.0f)
};

__device__ __forceinline__ float4 lerp4(float4 a, float4 b, float t) {
    float4 r;
    r.x = fmaf(b.x - a.x, t, a.x);
    r.y = fmaf(b.y - a.y, t, a.y);
    r.z = fmaf(b.z - a.z, t, a.z);
    r.w = fmaf(b.w - a.w, t, a.w);
    return r;
}

__device__ __forceinline__ float4 max4(float4 a, float4 b) {
    float4 r;
    r.x = fmaxf(a.x, b.x);
    r.y = fmaxf(a.y, b.y);
    r.z = fmaxf(a.z, b.z);
    r.w = fmaxf(a.w, b.w);
    return r;
}

__device__ __forceinline__ float4 scale4(float4 a, float s) {
    float4 r; r.x = a.x * s; r.y = a.y * s; r.z = a.z * s; r.w = a.w * s;
    return r;
}

__global__ __launch_bounds__(256, 4)
void roi_pool_kernel(const float* __restrict__ fm,
                     const float* __restrict__ props,
                     const int*   __restrict__ ishape,
                     float* __restrict__ out,
                     int N)
{
    __shared__ Axis sy[CROP];
    __shared__ Axis sx[CROP];

    const int n   = blockIdx.x;
    const int tx  = threadIdx.x;                    // 0..63: channel group (float4)
    const int ty  = threadIdx.y;                    // 0..3 : pooled-cell slice
    const int tid = ty * 64 + tx;

    // ---- Per-box axis parameters (28 threads, once per box) ----
    if (tid < 2 * CROP) {
        const float h = (float)ishape[0];
        const float w = (float)ishape[1];
        const float* p = props + (size_t)n * 4;
        const bool isY = (tid < CROP);
        const int  i   = isY ? tid : tid - CROP;
        const float c1 = isY ? (p[1] / h) : (p[0] / w);
        const float c2 = isY ? (p[3] / h) : (p[2] / w);
        const float D  = isY ? (float)(HF - 1) : (float)(WF - 1);
        const float step = (c2 - c1) * D / (float)(CROP - 1);
        const float s    = fmaf((float)i, step, c1 * D);
        const float f    = floorf(s);
        int i0 = (int)f;
        i0 = max(0, min(i0, (int)D));
        const int i1 = min(i0 + 1, (int)D);
        Axis a;
        a.i0 = i0;
        a.i1 = i1;
        a.l  = s - f;
        a.v  = (s >= 0.0f && s <= D) ? 1.0f : 0.0f;
        if (isY) sy[i] = a; else sx[i] = a;
    }
    __syncthreads();

    const int coff = tx * 4;  // channel offset for this lane's float4

    // ---- 49 pooled cells, strided over threadIdx.y ----
    for (int cell = ty; cell < POOL * POOL; cell += 4) {
        const int py = cell / POOL;
        const int px = cell - py * POOL;

        const Axis ax0 = sx[2 * px];
        const Axis ax1 = sx[2 * px + 1];

        // column byte-offsets (element offsets into a row) for the 4 x-corners
        const int c00 = ax0.i0 * CC + coff;   // sample dx=0, corner x0
        const int c01 = ax0.i1 * CC + coff;   // sample dx=0, corner x1
        const int c10 = ax1.i0 * CC + coff;   // sample dx=1, corner x0
        const int c11 = ax1.i1 * CC + coff;   // sample dx=1, corner x1

        float4 m = make_float4(-__FLT_MAX__, -__FLT_MAX__, -__FLT_MAX__, -__FLT_MAX__);

        #pragma unroll
        for (int dy = 0; dy < 2; ++dy) {
            const Axis ay = sy[2 * py + dy];
            const float* r0 = fm + (size_t)(ay.i0 * WF) * CC;
            const float* r1 = fm + (size_t)(ay.i1 * WF) * CC;

            // front-batch all 8 loads for this y-sample before any math
            const float4 a00 = *(const float4*)(r0 + c00);
            const float4 a01 = *(const float4*)(r0 + c01);
            const float4 a10 = *(const float4*)(r1 + c00);
            const float4 a11 = *(const float4*)(r1 + c01);
            const float4 b00 = *(const float4*)(r0 + c10);
            const float4 b01 = *(const float4*)(r0 + c11);
            const float4 b10 = *(const float4*)(r1 + c10);
            const float4 b11 = *(const float4*)(r1 + c11);

            const float ly = ay.l;
            const float va = ay.v * ax0.v;
            const float vb = ay.v * ax1.v;

            // sample (dy, dx=0)
            float4 ta = lerp4(a00, a01, ax0.l);
            float4 ba = lerp4(a10, a11, ax0.l);
            float4 sa = scale4(lerp4(ta, ba, ly), va);
            m = max4(m, sa);

            // sample (dy, dx=1)
            float4 tb = lerp4(b00, b01, ax1.l);
            float4 bb = lerp4(b10, b11, ax1.l);
            float4 sb = scale4(lerp4(tb, bb, ly), vb);
            m = max4(m, sb);
        }

        float* o = out + (((size_t)n * (POOL * POOL)) + cell) * CC + coff;
        __stcs((float4*)o, m);   // streaming store: don't evict the feature map from L2
    }
}

extern "C" void kernel_launch(void* const* d_in, const int* in_sizes, int n_in,
                              void* d_out, int out_size) {
    const float* fm     = (const float*)d_in[0];
    const float* props  = (const float*)d_in[1];
    const int*   ishape = (const int*)  d_in[2];
    float*       out    = (float*)d_out;

    const int N = in_sizes[1] / 4;   // proposals: [N, 4]

    dim3 block(64, 4, 1);
    dim3 grid(N, 1, 1);
    roi_pool_kernel<<<grid, block>>>(fm, props, ishape, out, N);
}